// round 7
// baseline (speedup 1.0000x reference)
#include <cuda_runtime.h>

// out = (Q K^T) V == Q (K^T V).  B=1, H=16, S=4096, D=64, fp32.
// Phase A: partial M_hc = K_chunk^T V_chunk  (f32x2 packed over s-pairs)
// Phase B: Mt[h][j][i] = sum_c partial[i][j]
// Phase C: out = Q @ M  (f32x2 packed over d-pairs)

#define NH      16
#define SS      4096
#define DD      64
#define CHUNKS  32
#define CHUNK_S 128          // rows per phase-A block (2 sub-tiles of 64)

__device__ float g_partial[NH * CHUNKS * DD * DD];  // 8.4 MB
__device__ float g_Mt[NH * DD * DD];                // 256 KB, Mt[h][j*64+i]

// packed fp32x2 FMA: d.lo += a.lo*b.lo ; d.hi += a.hi*b.hi
#define FFMA2(d, a, b) \
    asm("fma.rn.f32x2 %0, %1, %2, %0;" : "+l"(d) : "l"(a), "l"(b))

__device__ __forceinline__ float pairsum(unsigned long long v) {
    float lo, hi;
    asm("mov.b64 {%0, %1}, %2;" : "=f"(lo), "=f"(hi) : "l"(v));
    return lo + hi;
}

// ---------------------------------------------------------------------------
// Phase A: per-(head, chunk) partial K^T V with s-interleaved smem + f32x2.
// 256 threads as 16x16; thread (ty,tx) owns M[ty*4..+3][tx*4..+3].
// smem layout: ks2[s2*128 + d*2 + par] = K[2*s2+par][d]  (pairs along s)
// ---------------------------------------------------------------------------
__global__ __launch_bounds__(256, 4) void ktv_partial_kernel(
    const float* __restrict__ kg, const float* __restrict__ vg)
{
    __shared__ float ks2[32 * 128];   // 16 KB
    __shared__ float vs2[32 * 128];   // 16 KB

    const int bx    = blockIdx.x;
    const int h     = bx >> 5;
    const int chunk = bx & 31;
    const int tid   = threadIdx.x;
    const int ty    = tid >> 4;
    const int tx    = tid & 15;

    const float4* Kg = (const float4*)(kg + (h * SS + chunk * CHUNK_S) * DD);
    const float4* Vg = (const float4*)(vg + (h * SS + chunk * CHUNK_S) * DD);

    const ulonglong2* ksu = (const ulonglong2*)ks2;   // [s2*32 + d/2]
    const ulonglong2* vsu = (const ulonglong2*)vs2;

    unsigned long long acc[4][4];
    #pragma unroll
    for (int r = 0; r < 4; ++r)
        #pragma unroll
        for (int c = 0; c < 4; ++c) acc[r][c] = 0ULL;

    for (int sub = 0; sub < 2; ++sub) {
        // Stage 64x64 K and V tiles, scattering into s-interleaved layout.
        #pragma unroll
        for (int i = 0; i < 4; ++i) {
            int idx = tid + i * 256;          // float4 index into 64x64 tile
            int s   = idx >> 4;
            int d0  = (idx & 15) * 4;
            float4 kq = Kg[sub * 1024 + idx];
            float4 vq = Vg[sub * 1024 + idx];
            int base = (s >> 1) * 128 + (s & 1);
            ks2[base + (d0 + 0) * 2] = kq.x;
            ks2[base + (d0 + 1) * 2] = kq.y;
            ks2[base + (d0 + 2) * 2] = kq.z;
            ks2[base + (d0 + 3) * 2] = kq.w;
            vs2[base + (d0 + 0) * 2] = vq.x;
            vs2[base + (d0 + 1) * 2] = vq.y;
            vs2[base + (d0 + 2) * 2] = vq.z;
            vs2[base + (d0 + 3) * 2] = vq.w;
        }
        __syncthreads();

        #pragma unroll 4
        for (int s2 = 0; s2 < 32; ++s2) {
            ulonglong2 ka = ksu[s2 * 32 + ty * 2];       // broadcast across tx
            ulonglong2 kb = ksu[s2 * 32 + ty * 2 + 1];
            ulonglong2 va = vsu[s2 * 32 + tx * 2];
            ulonglong2 vb = vsu[s2 * 32 + tx * 2 + 1];
            unsigned long long kk[4] = {ka.x, ka.y, kb.x, kb.y};
            unsigned long long vv[4] = {va.x, va.y, vb.x, vb.y};
            #pragma unroll
            for (int r = 0; r < 4; ++r)
                #pragma unroll
                for (int c = 0; c < 4; ++c)
                    FFMA2(acc[r][c], kk[r], vv[c]);
        }
        __syncthreads();
    }

    float* P = g_partial + (h * CHUNKS + chunk) * DD * DD;
    #pragma unroll
    for (int r = 0; r < 4; ++r) {
        *(float4*)&P[(ty * 4 + r) * DD + tx * 4] =
            make_float4(pairsum(acc[r][0]), pairsum(acc[r][1]),
                        pairsum(acc[r][2]), pairsum(acc[r][3]));
    }
}

// ---------------------------------------------------------------------------
// Phase B: reduce 32 chunk-partials per head, write transposed Mt[h][j*64+i].
// ---------------------------------------------------------------------------
__global__ __launch_bounds__(256) void reduce_kernel()
{
    int base = blockIdx.x * 256 + threadIdx.x;   // grid 64 -> 16384 threads
    #pragma unroll
    for (int rep = 0; rep < 4; ++rep) {
        int o = base + rep * 16384;              // 0..65535
        int h = o >> 12;
        int e = o & 4095;                        // e = i*64 + j
        const float* P = g_partial + h * CHUNKS * 4096 + e;
        float sum = 0.f;
        #pragma unroll
        for (int c = 0; c < CHUNKS; ++c) sum += P[c * 4096];
        int i = e >> 6;
        int j = e & 63;
        g_Mt[h * 4096 + j * 64 + i] = sum;
    }
}

// ---------------------------------------------------------------------------
// Phase C: out = Q @ M with f32x2 over d-pairs (both operands contiguous
// along d: Q rows and Mt rows). Mt smem swizzled to break column conflicts.
// ---------------------------------------------------------------------------
__global__ __launch_bounds__(256, 4) void qm_kernel(
    const float* __restrict__ qg, float* __restrict__ outg)
{
    __shared__ float  qs[DD * DD];      // 16 KB
    __shared__ float4 mt4[DD * 16];     // 4 KB, swizzled by (j>>2)&7

    const int bx  = blockIdx.x;
    const int h   = bx >> 6;
    const int qt  = bx & 63;
    const int tid = threadIdx.x;
    const int ty  = tid >> 4;
    const int tx  = tid & 15;

    const float4* Qg = (const float4*)(qg + (h * SS + qt * 64) * DD);
    const float4* Mg = (const float4*)(g_Mt + h * 4096);
    float4* qs4 = (float4*)qs;

    #pragma unroll
    for (int it = 0; it < 4; ++it) {
        int o4 = tid + it * 256;                 // float4 index 0..1023
        qs4[o4] = Qg[o4];
        int j  = o4 >> 4;
        int d4 = o4 & 15;
        mt4[j * 16 + (d4 ^ ((j >> 2) & 7))] = Mg[o4];
    }
    __syncthreads();

    const ulonglong2* qsu = (const ulonglong2*)qs;    // [(row)*16 + d4]
    const ulonglong2* mtu = (const ulonglong2*)mt4;

    const int i0 = ty * 4;                       // q rows
    const int j0 = tx * 4;                       // out cols

    unsigned long long acc[4][4];
    #pragma unroll
    for (int r = 0; r < 4; ++r)
        #pragma unroll
        for (int c = 0; c < 4; ++c) acc[r][c] = 0ULL;

    #pragma unroll 4
    for (int d4 = 0; d4 < 16; ++d4) {
        ulonglong2 mv[4];
        #pragma unroll
        for (int c = 0; c < 4; ++c) {
            int j = j0 + c;
            mv[c] = mtu[j * 16 + (d4 ^ ((j >> 2) & 7))];
        }
        #pragma unroll
        for (int r = 0; r < 4; ++r) {
            ulonglong2 qv = qsu[(i0 + r) * 16 + d4];   // broadcast across tx
            #pragma unroll
            for (int c = 0; c < 4; ++c) {
                FFMA2(acc[r][c], qv.x, mv[c].x);
                FFMA2(acc[r][c], qv.y, mv[c].y);
            }
        }
    }

    float* O = outg + (h * SS + qt * 64) * DD;
    #pragma unroll
    for (int r = 0; r < 4; ++r) {
        *(float4*)&O[(i0 + r) * DD + j0] =
            make_float4(pairsum(acc[r][0]), pairsum(acc[r][1]),
                        pairsum(acc[r][2]), pairsum(acc[r][3]));
    }
}

// ---------------------------------------------------------------------------
extern "C" void kernel_launch(void* const* d_in, const int* in_sizes, int n_in,
                              void* d_out, int out_size)
{
    const float* q = (const float*)d_in[0];
    const float* k = (const float*)d_in[1];
    const float* v = (const float*)d_in[2];
    float* out = (float*)d_out;
    (void)in_sizes; (void)n_in; (void)out_size;

    ktv_partial_kernel<<<NH * CHUNKS, 256>>>(k, v);
    reduce_kernel<<<64, 256>>>();
    qm_kernel<<<NH * 64, 256>>>(q, out);
}

// round 10
// speedup vs baseline: 1.5548x; 1.5548x over previous
#include <cuda_runtime.h>

// out = (Q K^T) V == Q (K^T V).  B=1, H=16, S=4096, D=64, fp32.
// Phase A: partial M_hc = K_chunk^T V_chunk   (f32x2, dup-K, natural layout)
// Phase B: M[h] = sum_c partial               (coalesced, natural layout)
// Phase C: out = Q @ M                        (f32x2, dup-Q, natural layout)

#define NH      16
#define SS      4096
#define DD      64
#define CHUNKS  32
#define CHUNK_S 128          // rows per phase-A block (2 sub-tiles of 64)

__device__ float g_partial[NH * CHUNKS * DD * DD];  // 8.4 MB
__device__ float g_M[NH * DD * DD];                 // 256 KB, natural M[h][d*64+j]

// packed fp32x2 FMA: d.lo += a.lo*b.lo ; d.hi += a.hi*b.hi
#define FFMA2(d, a, b) \
    asm("fma.rn.f32x2 %0, %1, %2, %0;" : "+l"(d) : "l"(a), "l"(b))

__device__ __forceinline__ unsigned long long dup2(float f) {
    unsigned long long r;
    asm("mov.b64 %0, {%1, %1};" : "=l"(r) : "f"(f));
    return r;
}

// ---------------------------------------------------------------------------
// Phase A: per-(head, chunk) partial K^T V.
// 256 threads as 16x16; thread (ty,tx) owns M[ty*4..+3][tx*4..+3].
// Same smem access pattern as the proven scalar kernel (broadcast LDS.128 for
// K, conflict-free LDS.128 for V); packed math via register duplication of K.
// ---------------------------------------------------------------------------
__global__ __launch_bounds__(256) void ktv_partial_kernel(
    const float* __restrict__ kg, const float* __restrict__ vg)
{
    __shared__ float ks[DD * DD];   // 16 KB
    __shared__ float vs[DD * DD];   // 16 KB

    const int bx    = blockIdx.x;
    const int h     = bx >> 5;
    const int chunk = bx & 31;
    const int tid   = threadIdx.x;
    const int ty    = tid >> 4;
    const int tx    = tid & 15;

    const float4* Kg = (const float4*)(kg + (h * SS + chunk * CHUNK_S) * DD);
    const float4* Vg = (const float4*)(vg + (h * SS + chunk * CHUNK_S) * DD);
    float4* ks4 = (float4*)ks;
    float4* vs4 = (float4*)vs;

    unsigned long long acc[4][2];
    #pragma unroll
    for (int r = 0; r < 4; ++r) { acc[r][0] = 0ULL; acc[r][1] = 0ULL; }

    for (int sub = 0; sub < CHUNK_S / 64; ++sub) {
        #pragma unroll
        for (int i = 0; i < 4; ++i) {
            int idx = tid + i * 256;
            ks4[idx] = Kg[sub * 1024 + idx];
            vs4[idx] = Vg[sub * 1024 + idx];
        }
        __syncthreads();

        #pragma unroll 8
        for (int s = 0; s < 64; ++s) {
            float4     kk = *(const float4*)&ks[s * DD + ty * 4];     // broadcast
            ulonglong2 vv = *(const ulonglong2*)&vs[s * DD + tx * 4]; // conflict-free
            unsigned long long kd0 = dup2(kk.x);
            unsigned long long kd1 = dup2(kk.y);
            unsigned long long kd2 = dup2(kk.z);
            unsigned long long kd3 = dup2(kk.w);
            FFMA2(acc[0][0], kd0, vv.x); FFMA2(acc[0][1], kd0, vv.y);
            FFMA2(acc[1][0], kd1, vv.x); FFMA2(acc[1][1], kd1, vv.y);
            FFMA2(acc[2][0], kd2, vv.x); FFMA2(acc[2][1], kd2, vv.y);
            FFMA2(acc[3][0], kd3, vv.x); FFMA2(acc[3][1], kd3, vv.y);
        }
        __syncthreads();
    }

    float* P = g_partial + (h * CHUNKS + chunk) * DD * DD;
    #pragma unroll
    for (int r = 0; r < 4; ++r) {
        // acc pairs are bit-identical to 4 consecutive floats of the row.
        *(ulonglong2*)&P[(ty * 4 + r) * DD + tx * 4] =
            make_ulonglong2(acc[r][0], acc[r][1]);
    }
}

// ---------------------------------------------------------------------------
// Phase B: reduce 32 chunk-partials per head into natural-layout M.
// Fully coalesced reads and writes.
// ---------------------------------------------------------------------------
__global__ __launch_bounds__(256) void reduce_kernel()
{
    int o = blockIdx.x * 256 + threadIdx.x;      // grid 256 -> 65536 threads
    int h = o >> 12;
    int e = o & 4095;
    const float* P = g_partial + h * CHUNKS * 4096 + e;
    float sum = 0.f;
    #pragma unroll
    for (int c = 0; c < CHUNKS; ++c) sum += P[c * 4096];
    g_M[o] = sum;
}

// ---------------------------------------------------------------------------
// Phase C: out = Q @ M.  Block: 64 q-rows x 64 cols, 16x16 threads, 4x4 tile.
// M rows read conflict-free (contiguous j), Q scalars broadcast + duplicated.
// ---------------------------------------------------------------------------
__global__ __launch_bounds__(256) void qm_kernel(
    const float* __restrict__ qg, float* __restrict__ outg)
{
    __shared__ float qs[DD * DD];   // 16 KB
    __shared__ float ms[DD * DD];   // 16 KB

    const int bx  = blockIdx.x;
    const int h   = bx >> 6;
    const int qt  = bx & 63;
    const int tid = threadIdx.x;
    const int ty  = tid >> 4;
    const int tx  = tid & 15;

    const float4* Qg = (const float4*)(qg + (h * SS + qt * 64) * DD);
    const float4* Mg = (const float4*)(g_M + h * 4096);
    float4* qs4 = (float4*)qs;
    float4* ms4 = (float4*)ms;

    #pragma unroll
    for (int it = 0; it < 4; ++it) {
        int o4 = tid + it * 256;
        qs4[o4] = Qg[o4];
        ms4[o4] = Mg[o4];
    }
    __syncthreads();

    const int i0 = ty * 4;
    unsigned long long acc[4][2];
    #pragma unroll
    for (int r = 0; r < 4; ++r) { acc[r][0] = 0ULL; acc[r][1] = 0ULL; }

    #pragma unroll 4
    for (int d4 = 0; d4 < 16; ++d4) {
        float4 qv[4];
        #pragma unroll
        for (int r = 0; r < 4; ++r)
            qv[r] = *(const float4*)&qs[(i0 + r) * DD + d4 * 4];   // broadcast
        #pragma unroll
        for (int dd = 0; dd < 4; ++dd) {
            ulonglong2 mv =
                *(const ulonglong2*)&ms[(d4 * 4 + dd) * DD + tx * 4]; // conflict-free
            #pragma unroll
            for (int r = 0; r < 4; ++r) {
                unsigned long long qd = dup2(((const float*)&qv[r])[dd]);
                FFMA2(acc[r][0], qd, mv.x);
                FFMA2(acc[r][1], qd, mv.y);
            }
        }
    }

    float* O = outg + (h * SS + qt * 64) * DD;
    #pragma unroll
    for (int r = 0; r < 4; ++r) {
        *(ulonglong2*)&O[(i0 + r) * DD + tx * 4] =
            make_ulonglong2(acc[r][0], acc[r][1]);
    }
}

// ---------------------------------------------------------------------------
extern "C" void kernel_launch(void* const* d_in, const int* in_sizes, int n_in,
                              void* d_out, int out_size)
{
    const float* q = (const float*)d_in[0];
    const float* k = (const float*)d_in[1];
    const float* v = (const float*)d_in[2];
    float* out = (float*)d_out;
    (void)in_sizes; (void)n_in; (void)out_size;

    ktv_partial_kernel<<<NH * CHUNKS, 256>>>(k, v);
    reduce_kernel<<<256, 256>>>();
    qm_kernel<<<NH * 64, 256>>>(q, out);
}